// round 1
// baseline (speedup 1.0000x reference)
#include <cuda_runtime.h>
#include <cstdint>

#define N_NODES 50000
#define N_EDGES 800000
#define CH 128
#define OUTC 64
#define NG 256

#define GEMM_ROWS 32
#define GEMM_THREADS 128
#define XS_STRIDE 36
#define GEMM_SMEM ((CH*CH + CH*XS_STRIDE) * 4)

// ---------------- scratch (device globals; no allocation allowed) ----------
__device__ int g_is64_ei;
__device__ int g_is64_b;
__device__ int g_src[N_EDGES];
__device__ int g_dst[N_EDGES];
__device__ int g_csr_src[N_EDGES];
__device__ int g_counts[N_NODES];
__device__ int g_cstart[N_NODES + 1];
__device__ int g_cursor[N_NODES];
__device__ float g_dinv[N_NODES];
__device__ int g_batch[N_NODES];
__device__ float g_h[(size_t)N_NODES * CH];
__device__ unsigned g_pooled[NG * CH];

// ---------------- dtype sniffing -------------------------------------------
// If arrays are int64 (little-endian, values < 50000 => high 32-bit word == 0),
// every odd 32-bit word is zero. If int32, sampled words are node/graph ids
// that are essentially never all zero (batch sampled at indices > 2000 since
// it is sorted and early entries are legitimately 0).
__global__ void k_detect(const unsigned* __restrict__ ei,
                         const unsigned* __restrict__ bt) {
    int w = threadIdx.x >> 5, lane = threadIdx.x & 31;
    if (w == 0) {
        unsigned v = ei[2 * lane * 999 + 1];          // odd idx, < 2*E words
        unsigned m = __ballot_sync(0xffffffffu, v == 0u);
        if (lane == 0) g_is64_ei = (m == 0xffffffffu);
    } else {
        unsigned v = bt[2001 + 2 * lane * 747];       // odd idx, < N words
        unsigned m = __ballot_sync(0xffffffffu, v == 0u);
        if (lane == 0) g_is64_b = (m == 0xffffffffu);
    }
}

__global__ void k_reset() {
    int i = blockIdx.x * blockDim.x + threadIdx.x;
    if (i < N_NODES) g_counts[i] = 0;
    if (i < NG * CH) g_pooled[i] = 0u;                // 0u == 0.0f bits
}

__global__ void k_convert_batch(const unsigned* __restrict__ bt) {
    int i = blockIdx.x * blockDim.x + threadIdx.x;
    if (i >= N_NODES) return;
    g_batch[i] = (int)(g_is64_b ? bt[2 * i] : bt[i]);
}

__global__ void k_convert_edges(const unsigned* __restrict__ ei) {
    int e = blockIdx.x * blockDim.x + threadIdx.x;
    if (e >= N_EDGES) return;
    int s, d;
    if (g_is64_ei) {
        s = (int)ei[2 * e];
        d = (int)ei[2 * N_EDGES + 2 * e];
    } else {
        s = (int)ei[e];
        d = (int)ei[N_EDGES + e];
    }
    g_src[e] = s;
    g_dst[e] = d;
    atomicAdd(&g_counts[d], 1);
}

// Single-block exclusive scan over 50000 counts; also writes dinv = rsqrt(deg)
// with deg = in_count + 1 (self loop).
__global__ void k_scan() {
    __shared__ int ss[1024];
    const int CHUNK = 49;                              // 49*1024 >= 50000
    int t = threadIdx.x;
    int base = t * CHUNK;
    int local = 0;
    for (int i = 0; i < CHUNK; i++) {
        int idx = base + i;
        if (idx < N_NODES) local += g_counts[idx];
    }
    ss[t] = local;
    __syncthreads();
    for (int off = 1; off < 1024; off <<= 1) {
        int v = (t >= off) ? ss[t - off] : 0;
        __syncthreads();
        ss[t] += v;
        __syncthreads();
    }
    int run = ss[t] - local;                           // exclusive prefix
    for (int i = 0; i < CHUNK; i++) {
        int idx = base + i;
        if (idx < N_NODES) {
            g_cstart[idx] = run;
            g_cursor[idx] = run;
            int c = g_counts[idx];
            g_dinv[idx] = rsqrtf((float)(c + 1));
            run += c;
        }
    }
    if (t == 0) g_cstart[N_NODES] = ss[1023];
}

__global__ void k_fill() {
    int e = blockIdx.x * blockDim.x + threadIdx.x;
    if (e >= N_EDGES) return;
    int d = g_dst[e];
    int pos = atomicAdd(&g_cursor[d], 1);
    g_csr_src[pos] = g_src[e];
}

// ---------------- h = x @ W1 ----------------------------------------------
// 32 rows x 128 cols per block. W1 (64KB) + transposed x tile in smem.
// 8x4 register micro-tile: per k, 2 LDS.128 (x, broadcast) + 1 LDS.128 (w)
// feed 32 FFMAs.
__global__ void __launch_bounds__(GEMM_THREADS) k_gemm(
        const float* __restrict__ x, const float* __restrict__ W1) {
    extern __shared__ float sm[];
    float* Wsh = sm;                 // [128][128]
    float* xsT = sm + CH * CH;       // [128][36] transposed, padded
    int tid = threadIdx.x;
    int row0 = blockIdx.x * GEMM_ROWS;

    for (int idx = tid; idx < CH * CH; idx += GEMM_THREADS)
        Wsh[idx] = W1[idx];
    for (int idx = tid; idx < GEMM_ROWS * CH; idx += GEMM_THREADS) {
        int r = idx >> 7, k = idx & 127;
        int gr = row0 + r;
        xsT[k * XS_STRIDE + r] = (gr < N_NODES) ? x[(size_t)gr * CH + k] : 0.f;
    }
    __syncthreads();

    int tx = tid & 31, ty = tid >> 5;
    int col0 = tx * 4, r0 = ty * 8;
    float4 acc[8];
#pragma unroll
    for (int i = 0; i < 8; i++) acc[i] = make_float4(0.f, 0.f, 0.f, 0.f);

#pragma unroll 8
    for (int k = 0; k < CH; k++) {
        float4 w  = *(const float4*)&Wsh[k * CH + col0];
        float4 xa = *(const float4*)&xsT[k * XS_STRIDE + r0];
        float4 xb = *(const float4*)&xsT[k * XS_STRIDE + r0 + 4];
        float xr[8] = {xa.x, xa.y, xa.z, xa.w, xb.x, xb.y, xb.z, xb.w};
#pragma unroll
        for (int i = 0; i < 8; i++) {
            acc[i].x = fmaf(xr[i], w.x, acc[i].x);
            acc[i].y = fmaf(xr[i], w.y, acc[i].y);
            acc[i].z = fmaf(xr[i], w.z, acc[i].z);
            acc[i].w = fmaf(xr[i], w.w, acc[i].w);
        }
    }
#pragma unroll
    for (int i = 0; i < 8; i++) {
        int gr = row0 + r0 + i;
        if (gr < N_NODES)
            *(float4*)&g_h[(size_t)gr * CH + col0] = acc[i];
    }
}

// ---------------- aggregation + bias + relu + max-pool (fused) -------------
// Warp per dst node. acc = dinv[d]*(sum_e dinv[s]*h[s] + dinv[d]*h[d]) + b1,
// relu'd, then atomicMax-as-uint into pooled (valid: all values >= 0).
__global__ void k_aggregate(const float* __restrict__ b1) {
    int gw = (blockIdx.x * blockDim.x + threadIdx.x) >> 5;
    int lane = threadIdx.x & 31;
    if (gw >= N_NODES) return;
    int d = gw;
    float di = g_dinv[d];
    const float4* __restrict__ h4 = (const float4*)g_h;

    float4 acc = h4[d * 32 + lane];                    // self loop
    acc.x *= di; acc.y *= di; acc.z *= di; acc.w *= di;

    int e0 = g_cstart[d], e1 = g_cstart[d + 1];
    for (int e = e0; e < e1; e++) {
        int s = g_csr_src[e];
        float w = g_dinv[s];
        float4 hv = h4[s * 32 + lane];
        acc.x = fmaf(w, hv.x, acc.x);
        acc.y = fmaf(w, hv.y, acc.y);
        acc.z = fmaf(w, hv.z, acc.z);
        acc.w = fmaf(w, hv.w, acc.w);
    }
    float4 bb = *(const float4*)&b1[lane * 4];
    float vx = fmaxf(fmaf(acc.x, di, bb.x), 0.f);
    float vy = fmaxf(fmaf(acc.y, di, bb.y), 0.f);
    float vz = fmaxf(fmaf(acc.z, di, bb.z), 0.f);
    float vw = fmaxf(fmaf(acc.w, di, bb.w), 0.f);

    int g = g_batch[d];
    unsigned* P = &g_pooled[g * CH + lane * 4];
    atomicMax(&P[0], __float_as_uint(vx));
    atomicMax(&P[1], __float_as_uint(vy));
    atomicMax(&P[2], __float_as_uint(vz));
    atomicMax(&P[3], __float_as_uint(vw));
}

// ---------------- out = relu(pooled @ W2 + b2) -----------------------------
__global__ void k_out(const float* __restrict__ W2, const float* __restrict__ b2,
                      float* __restrict__ out) {
    __shared__ float p[CH];
    int g = blockIdx.x, c = threadIdx.x;
    p[c]      = __uint_as_float(g_pooled[g * CH + c]);
    p[c + 64] = __uint_as_float(g_pooled[g * CH + c + 64]);
    __syncthreads();
    float acc = b2[c];
#pragma unroll 8
    for (int k = 0; k < CH; k++)
        acc = fmaf(p[k], W2[k * OUTC + c], acc);
    out[g * OUTC + c] = fmaxf(acc, 0.f);
}

// ---------------- launch ---------------------------------------------------
extern "C" void kernel_launch(void* const* d_in, const int* in_sizes, int n_in,
                              void* d_out, int out_size) {
    // Identify inputs by (unique) element counts; robust to metadata order.
    const float *x = nullptr, *W1 = nullptr, *b1 = nullptr, *W2 = nullptr, *b2 = nullptr;
    const unsigned *ei = nullptr, *bt = nullptr;
    for (int i = 0; i < n_in; i++) {
        switch (in_sizes[i]) {
            case N_NODES * CH:    x  = (const float*)d_in[i]; break;    // 6.4M
            case 2 * N_EDGES:     ei = (const unsigned*)d_in[i]; break; // 1.6M
            case N_NODES:         bt = (const unsigned*)d_in[i]; break; // 50k
            case CH * CH:         W1 = (const float*)d_in[i]; break;    // 16384
            case CH:              b1 = (const float*)d_in[i]; break;    // 128
            case CH * OUTC:       W2 = (const float*)d_in[i]; break;    // 8192
            case OUTC:            b2 = (const float*)d_in[i]; break;    // 64
        }
    }
    float* out = (float*)d_out;

    cudaFuncSetAttribute(k_gemm, cudaFuncAttributeMaxDynamicSharedMemorySize,
                         GEMM_SMEM);

    k_detect<<<1, 64>>>(ei, bt);
    k_reset<<<(N_NODES + 255) / 256, 256>>>();
    k_convert_batch<<<(N_NODES + 255) / 256, 256>>>(bt);
    k_convert_edges<<<(N_EDGES + 255) / 256, 256>>>(ei);
    k_scan<<<1, 1024>>>();
    k_fill<<<(N_EDGES + 255) / 256, 256>>>();
    k_gemm<<<(N_NODES + GEMM_ROWS - 1) / GEMM_ROWS, GEMM_THREADS, GEMM_SMEM>>>(x, W1);
    k_aggregate<<<(N_NODES * 32 + 255) / 256, 256>>>(b1);
    k_out<<<NG, OUTC>>>(W2, b2, out);
}

// round 2
// speedup vs baseline: 2.4328x; 2.4328x over previous
#include <cuda_runtime.h>
#include <cstdint>

#define N_NODES 50000
#define N_EDGES 800000
#define CH 128
#define OUTC 64
#define NG 256

#define GEMM_ROWS 64
#define GEMM_THREADS 256
#define XS_STRIDE 68
#define GEMM_SMEM ((CH*CH + CH*XS_STRIDE) * 4)

#define SCAN_B 196            // ceil(50000/256)
#define AGG_WARPS 16          // nodes per aggregate block (50000 % 16 == 0 -> 3125 blocks)

// ---------------- scratch (device globals; no allocation allowed) ----------
__device__ int g_is64_ei;
__device__ int g_is64_b;
__device__ int g_src[N_EDGES];
__device__ int g_dst[N_EDGES];
__device__ int g_csr_src[N_EDGES];
__device__ int g_counts[N_NODES];
__device__ int g_cstart[N_NODES + 1];
__device__ int g_cursor[N_NODES];
__device__ float g_dinv[N_NODES];
__device__ int g_batch[N_NODES];
__device__ float g_h[(size_t)N_NODES * CH];
__device__ unsigned g_pooled[NG * CH];
__device__ int g_bsum[256];
__device__ int g_boff[256];

// ---------------- init: dtype sniffing + zero counts/pooled ----------------
// int64 little-endian with values < 50000 => every odd 32-bit word is zero.
// batch sampled at indices > 2000 (sorted, so values there are nonzero graph ids).
__global__ void k_init(const unsigned* __restrict__ ei,
                       const unsigned* __restrict__ bt) {
    int i = blockIdx.x * blockDim.x + threadIdx.x;
    if (i < N_NODES) g_counts[i] = 0;
    if (i < NG * CH) g_pooled[i] = 0u;               // 0u == 0.0f bits
    if (blockIdx.x == 0 && threadIdx.x < 64) {
        int w = threadIdx.x >> 5, lane = threadIdx.x & 31;
        if (w == 0) {
            unsigned v = ei[2 * lane * 999 + 1];
            unsigned m = __ballot_sync(0xffffffffu, v == 0u);
            if (lane == 0) g_is64_ei = (m == 0xffffffffu);
        } else {
            unsigned v = bt[2001 + 2 * lane * 747];
            unsigned m = __ballot_sync(0xffffffffu, v == 0u);
            if (lane == 0) g_is64_b = (m == 0xffffffffu);
        }
    }
}

// ---------------- convert edges (+count) and batch -------------------------
__global__ void k_prep(const unsigned* __restrict__ ei,
                       const unsigned* __restrict__ bt) {
    int e = blockIdx.x * blockDim.x + threadIdx.x;
    if (e < N_NODES)
        g_batch[e] = (int)(g_is64_b ? bt[2 * e] : bt[e]);
    if (e >= N_EDGES) return;
    int s, d;
    if (g_is64_ei) {
        uint2 a = ((const uint2*)ei)[e];
        uint2 b = ((const uint2*)ei)[N_EDGES + e];
        s = (int)a.x; d = (int)b.x;
    } else {
        s = (int)ei[e];
        d = (int)ei[N_EDGES + e];
    }
    g_src[e] = s;
    g_dst[e] = d;
    atomicAdd(&g_counts[d], 1);
}

// ---------------- coalesced 3-phase exclusive scan -------------------------
__global__ void k_scan1() {
    __shared__ int ss[256];
    int t = threadIdx.x;
    int idx = blockIdx.x * 256 + t;
    int v = (idx < N_NODES) ? g_counts[idx] : 0;
    ss[t] = v; __syncthreads();
    for (int off = 128; off > 0; off >>= 1) {
        if (t < off) ss[t] += ss[t + off];
        __syncthreads();
    }
    if (t == 0) g_bsum[blockIdx.x] = ss[0];
}

__global__ void k_scan2() {
    __shared__ int ss[256];
    int t = threadIdx.x;
    int v = (t < SCAN_B) ? g_bsum[t] : 0;
    ss[t] = v; __syncthreads();
    for (int off = 1; off < 256; off <<= 1) {
        int u = (t >= off) ? ss[t - off] : 0;
        __syncthreads();
        ss[t] += u;
        __syncthreads();
    }
    g_boff[t] = ss[t] - v;                           // exclusive
    if (t == 255) g_cstart[N_NODES] = ss[255];
}

__global__ void k_scan3() {
    __shared__ int ss[256];
    int t = threadIdx.x;
    int idx = blockIdx.x * 256 + t;
    int c = (idx < N_NODES) ? g_counts[idx] : 0;
    ss[t] = c; __syncthreads();
    for (int off = 1; off < 256; off <<= 1) {
        int u = (t >= off) ? ss[t - off] : 0;
        __syncthreads();
        ss[t] += u;
        __syncthreads();
    }
    if (idx < N_NODES) {
        int start = g_boff[blockIdx.x] + ss[t] - c;  // exclusive prefix
        g_cstart[idx] = start;
        g_cursor[idx] = start;
        g_dinv[idx] = rsqrtf((float)(c + 1));
    }
}

__global__ void k_fill() {
    int e = blockIdx.x * blockDim.x + threadIdx.x;
    if (e >= N_EDGES) return;
    int d = g_dst[e];
    int pos = atomicAdd(&g_cursor[d], 1);
    g_csr_src[pos] = g_src[e];
}

// ---------------- h = x @ W1 ----------------------------------------------
// 64 rows x 128 cols per block, 256 threads, 8x4 register micro-tile.
__global__ void __launch_bounds__(GEMM_THREADS) k_gemm(
        const float* __restrict__ x, const float* __restrict__ W1) {
    extern __shared__ float sm[];
    float* Wsh = sm;                 // [128][128]
    float* xsT = sm + CH * CH;       // [128][68] transposed, padded
    int tid = threadIdx.x;
    int row0 = blockIdx.x * GEMM_ROWS;

    for (int idx = tid; idx < CH * CH; idx += GEMM_THREADS)
        Wsh[idx] = W1[idx];
    for (int idx = tid; idx < GEMM_ROWS * CH; idx += GEMM_THREADS) {
        int r = idx >> 7, k = idx & 127;
        int gr = row0 + r;
        xsT[k * XS_STRIDE + r] = (gr < N_NODES) ? x[(size_t)gr * CH + k] : 0.f;
    }
    __syncthreads();

    int tx = tid & 31, ty = tid >> 5;
    int col0 = tx * 4, r0 = ty * 8;
    float4 acc[8];
#pragma unroll
    for (int i = 0; i < 8; i++) acc[i] = make_float4(0.f, 0.f, 0.f, 0.f);

#pragma unroll 8
    for (int k = 0; k < CH; k++) {
        float4 w  = *(const float4*)&Wsh[k * CH + col0];
        float4 xa = *(const float4*)&xsT[k * XS_STRIDE + r0];
        float4 xb = *(const float4*)&xsT[k * XS_STRIDE + r0 + 4];
        float xr[8] = {xa.x, xa.y, xa.z, xa.w, xb.x, xb.y, xb.z, xb.w};
#pragma unroll
        for (int i = 0; i < 8; i++) {
            acc[i].x = fmaf(xr[i], w.x, acc[i].x);
            acc[i].y = fmaf(xr[i], w.y, acc[i].y);
            acc[i].z = fmaf(xr[i], w.z, acc[i].z);
            acc[i].w = fmaf(xr[i], w.w, acc[i].w);
        }
    }
#pragma unroll
    for (int i = 0; i < 8; i++) {
        int gr = row0 + r0 + i;
        if (gr < N_NODES)
            *(float4*)&g_h[(size_t)gr * CH + col0] = acc[i];
    }
}

// ---------------- aggregation + bias + relu + pooled max (fused) -----------
// Warp per dst node; block (16 warps) reduces pooled-max in smem before the
// global atomics (batch is sorted, so a block spans 1-2 graphs).
__global__ void __launch_bounds__(AGG_WARPS * 32) k_aggregate(
        const float* __restrict__ b1) {
    __shared__ float sval[AGG_WARPS * CH];
    __shared__ int sgid[AGG_WARPS];
    int tid = threadIdx.x;
    int w = tid >> 5, lane = tid & 31;
    int d = blockIdx.x * AGG_WARPS + w;              // always < N_NODES (50000 % 16 == 0)

    float di = g_dinv[d];
    const float4* __restrict__ h4 = (const float4*)g_h;

    float4 acc = h4[d * 32 + lane];                  // self loop
    acc.x *= di; acc.y *= di; acc.z *= di; acc.w *= di;

    int e0 = g_cstart[d], e1 = g_cstart[d + 1];
    for (int e = e0; e < e1; e++) {
        int s = g_csr_src[e];
        float wn = g_dinv[s];
        float4 hv = h4[s * 32 + lane];
        acc.x = fmaf(wn, hv.x, acc.x);
        acc.y = fmaf(wn, hv.y, acc.y);
        acc.z = fmaf(wn, hv.z, acc.z);
        acc.w = fmaf(wn, hv.w, acc.w);
    }
    float4 bb = *(const float4*)&b1[lane * 4];
    float4 v;
    v.x = fmaxf(fmaf(acc.x, di, bb.x), 0.f);
    v.y = fmaxf(fmaf(acc.y, di, bb.y), 0.f);
    v.z = fmaxf(fmaf(acc.z, di, bb.z), 0.f);
    v.w = fmaxf(fmaf(acc.w, di, bb.w), 0.f);
    *(float4*)&sval[w * CH + lane * 4] = v;
    if (lane == 0) sgid[w] = g_batch[d];
    __syncthreads();

    if (tid < CH) {
        int c = tid;
        int curg = sgid[0];
        float m = sval[c];
        for (int ww = 1; ww < AGG_WARPS; ww++) {
            int g = sgid[ww];
            float u = sval[ww * CH + c];
            if (g == curg) {
                m = fmaxf(m, u);
            } else {
                atomicMax(&g_pooled[curg * CH + c], __float_as_uint(m));
                curg = g; m = u;
            }
        }
        atomicMax(&g_pooled[curg * CH + c], __float_as_uint(m));
    }
}

// ---------------- out = relu(pooled @ W2 + b2) -----------------------------
__global__ void k_out(const float* __restrict__ W2, const float* __restrict__ b2,
                      float* __restrict__ out) {
    __shared__ float p[CH];
    int g = blockIdx.x, c = threadIdx.x;
    p[c]      = __uint_as_float(g_pooled[g * CH + c]);
    p[c + 64] = __uint_as_float(g_pooled[g * CH + c + 64]);
    __syncthreads();
    float acc = b2[c];
#pragma unroll 8
    for (int k = 0; k < CH; k++)
        acc = fmaf(p[k], W2[k * OUTC + c], acc);
    out[g * OUTC + c] = fmaxf(acc, 0.f);
}

// ---------------- launch ---------------------------------------------------
extern "C" void kernel_launch(void* const* d_in, const int* in_sizes, int n_in,
                              void* d_out, int out_size) {
    const float *x = nullptr, *W1 = nullptr, *b1 = nullptr, *W2 = nullptr, *b2 = nullptr;
    const unsigned *ei = nullptr, *bt = nullptr;
    for (int i = 0; i < n_in; i++) {
        switch (in_sizes[i]) {
            case N_NODES * CH:    x  = (const float*)d_in[i]; break;
            case 2 * N_EDGES:     ei = (const unsigned*)d_in[i]; break;
            case N_NODES:         bt = (const unsigned*)d_in[i]; break;
            case CH * CH:         W1 = (const float*)d_in[i]; break;
            case CH:              b1 = (const float*)d_in[i]; break;
            case CH * OUTC:       W2 = (const float*)d_in[i]; break;
            case OUTC:            b2 = (const float*)d_in[i]; break;
        }
    }
    float* out = (float*)d_out;

    static cudaStream_t sB = nullptr;
    static cudaEvent_t evFork = nullptr, evJoin = nullptr;
    if (!sB) {
        cudaStreamCreateWithFlags(&sB, cudaStreamNonBlocking);
        cudaEventCreateWithFlags(&evFork, cudaEventDisableTiming);
        cudaEventCreateWithFlags(&evJoin, cudaEventDisableTiming);
        cudaFuncSetAttribute(k_gemm, cudaFuncAttributeMaxDynamicSharedMemorySize,
                             GEMM_SMEM);
    }

    // Fork: GEMM (independent of edge preprocessing) overlaps the prep chain.
    cudaEventRecord(evFork, 0);
    cudaStreamWaitEvent(sB, evFork, 0);
    k_gemm<<<(N_NODES + GEMM_ROWS - 1) / GEMM_ROWS, GEMM_THREADS, GEMM_SMEM, sB>>>(x, W1);
    cudaEventRecord(evJoin, sB);

    // Prep chain on the capture stream.
    k_init<<<SCAN_B, 256>>>(ei, bt);
    k_prep<<<(N_EDGES + 255) / 256, 256>>>(ei, bt);
    k_scan1<<<SCAN_B, 256>>>();
    k_scan2<<<1, 256>>>();
    k_scan3<<<SCAN_B, 256>>>();
    k_fill<<<(N_EDGES + 255) / 256, 256>>>();

    // Join: aggregation needs g_h from the GEMM.
    cudaStreamWaitEvent(0, evJoin, 0);
    k_aggregate<<<N_NODES / AGG_WARPS, AGG_WARPS * 32>>>(b1);
    k_out<<<NG, OUTC>>>(W2, b2, out);
}

// round 3
// speedup vs baseline: 2.8077x; 1.1541x over previous
#include <cuda_runtime.h>
#include <cuda_fp16.h>
#include <cstdint>

#define N_NODES 50000
#define N_EDGES 800000
#define CH 128
#define OUTC 64
#define NG 256

#define GEMM_ROWS 64
#define GEMM_THREADS 256
#define XS_STRIDE 68
#define GEMM_SMEM ((CH*CH + CH*XS_STRIDE) * 4)

#define SCAN_B 196            // ceil(50000/256)
#define AGG_WARPS 16          // nodes per aggregate block

// packed fp32x2 helpers (Blackwell FFMA2 path — only reachable via PTX)
#define FMA2(acc, a, b) \
    asm("fma.rn.f32x2 %0, %1, %2, %0;" : "+l"(acc) : "l"(a), "l"(b))
#define DUPF(dst, f) \
    asm("mov.b64 %0, {%1, %1};" : "=l"(dst) : "r"(__float_as_uint(f)))
#define UNPACK2(lo, hi, src) \
    asm("mov.b64 {%0, %1}, %2;" : "=r"(lo), "=r"(hi) : "l"(src))

// ---------------- scratch (device globals; no allocation allowed) ----------
__device__ int g_is64_ei;
__device__ int g_is64_b;
__device__ int g_src[N_EDGES];
__device__ int g_dst[N_EDGES];
__device__ int g_csr_src[N_EDGES];
__device__ int g_counts[N_NODES];
__device__ int g_cstart[N_NODES + 1];
__device__ int g_cursor[N_NODES];
__device__ float g_dinv[N_NODES];
__device__ int g_batch[N_NODES];
__device__ __half g_h[(size_t)N_NODES * CH];   // fp16 hidden features
__device__ unsigned g_pooled[NG * CH];
__device__ int g_bsum[256];
__device__ int g_boff[256];

// ---------------- init: dtype sniffing + zero counts/pooled ----------------
__global__ void k_init(const unsigned* __restrict__ ei,
                       const unsigned* __restrict__ bt) {
    int i = blockIdx.x * blockDim.x + threadIdx.x;
    if (i < N_NODES) g_counts[i] = 0;
    if (i < NG * CH) g_pooled[i] = 0u;               // 0u == 0.0f bits
    if (blockIdx.x == 0 && threadIdx.x < 64) {
        int w = threadIdx.x >> 5, lane = threadIdx.x & 31;
        if (w == 0) {
            unsigned v = ei[2 * lane * 999 + 1];
            unsigned m = __ballot_sync(0xffffffffu, v == 0u);
            if (lane == 0) g_is64_ei = (m == 0xffffffffu);
        } else {
            unsigned v = bt[2001 + 2 * lane * 747];
            unsigned m = __ballot_sync(0xffffffffu, v == 0u);
            if (lane == 0) g_is64_b = (m == 0xffffffffu);
        }
    }
}

// ---------------- convert edges (+count) and batch, 2 per thread -----------
__global__ void k_prep(const unsigned* __restrict__ ei,
                       const unsigned* __restrict__ bt) {
    int t = blockIdx.x * blockDim.x + threadIdx.x;
    if (t < N_NODES / 2) {
        int b0, b1;
        if (g_is64_b) {
            uint4 v = ((const uint4*)bt)[t];
            b0 = (int)v.x; b1 = (int)v.z;
        } else {
            uint2 v = ((const uint2*)bt)[t];
            b0 = (int)v.x; b1 = (int)v.y;
        }
        *(int2*)&g_batch[2 * t] = make_int2(b0, b1);
    }
    if (t >= N_EDGES / 2) return;
    int s0, s1, d0, d1;
    if (g_is64_ei) {
        uint4 a = ((const uint4*)ei)[t];
        uint4 b = ((const uint4*)ei)[N_EDGES / 2 + t];
        s0 = (int)a.x; s1 = (int)a.z;
        d0 = (int)b.x; d1 = (int)b.z;
    } else {
        uint2 a = ((const uint2*)ei)[t];
        uint2 b = ((const uint2*)ei)[N_EDGES / 2 + t];
        s0 = (int)a.x; s1 = (int)a.y;
        d0 = (int)b.x; d1 = (int)b.y;
    }
    *(int2*)&g_src[2 * t] = make_int2(s0, s1);
    *(int2*)&g_dst[2 * t] = make_int2(d0, d1);
    atomicAdd(&g_counts[d0], 1);
    atomicAdd(&g_counts[d1], 1);
}

// ---------------- coalesced 3-phase exclusive scan -------------------------
__global__ void k_scan1() {
    __shared__ int ss[256];
    int t = threadIdx.x;
    int idx = blockIdx.x * 256 + t;
    int v = (idx < N_NODES) ? g_counts[idx] : 0;
    ss[t] = v; __syncthreads();
    for (int off = 128; off > 0; off >>= 1) {
        if (t < off) ss[t] += ss[t + off];
        __syncthreads();
    }
    if (t == 0) g_bsum[blockIdx.x] = ss[0];
}

__global__ void k_scan2() {
    __shared__ int ss[256];
    int t = threadIdx.x;
    int v = (t < SCAN_B) ? g_bsum[t] : 0;
    ss[t] = v; __syncthreads();
    for (int off = 1; off < 256; off <<= 1) {
        int u = (t >= off) ? ss[t - off] : 0;
        __syncthreads();
        ss[t] += u;
        __syncthreads();
    }
    g_boff[t] = ss[t] - v;                           // exclusive
    if (t == 255) g_cstart[N_NODES] = ss[255];
}

__global__ void k_scan3() {
    __shared__ int ss[256];
    int t = threadIdx.x;
    int idx = blockIdx.x * 256 + t;
    int c = (idx < N_NODES) ? g_counts[idx] : 0;
    ss[t] = c; __syncthreads();
    for (int off = 1; off < 256; off <<= 1) {
        int u = (t >= off) ? ss[t - off] : 0;
        __syncthreads();
        ss[t] += u;
        __syncthreads();
    }
    if (idx < N_NODES) {
        int start = g_boff[blockIdx.x] + ss[t] - c;  // exclusive prefix
        g_cstart[idx] = start;
        g_cursor[idx] = start;
        g_dinv[idx] = rsqrtf((float)(c + 1));
    }
}

__global__ void k_fill() {
    int t = blockIdx.x * blockDim.x + threadIdx.x;
    if (t >= N_EDGES / 2) return;
    int2 d = *(const int2*)&g_dst[2 * t];
    int2 s = *(const int2*)&g_src[2 * t];
    int p0 = atomicAdd(&g_cursor[d.x], 1);
    g_csr_src[p0] = s.x;
    int p1 = atomicAdd(&g_cursor[d.y], 1);
    g_csr_src[p1] = s.y;
}

// ---------------- h = x @ W1 (fp32 inputs, FFMA2 core, fp16 store) ---------
// 64 rows x 128 cols per block, 256 threads. Register tile 8 rows x 4 cols,
// held as 4 row-pairs x 4 cols of packed f32x2. Per k: 3 LDS.128 + 4 dup
// movs + 16 FFMA2 (vs 32 FFMA scalar).
__global__ void __launch_bounds__(GEMM_THREADS) k_gemm(
        const float* __restrict__ x, const float* __restrict__ W1) {
    extern __shared__ float sm[];
    float* Wsh = sm;                 // [128][128]
    float* xsT = sm + CH * CH;       // [128][68] transposed, padded
    int tid = threadIdx.x;
    int row0 = blockIdx.x * GEMM_ROWS;

    for (int idx = tid; idx < CH * CH; idx += GEMM_THREADS)
        Wsh[idx] = W1[idx];
    for (int idx = tid; idx < GEMM_ROWS * CH; idx += GEMM_THREADS) {
        int r = idx >> 7, k = idx & 127;
        int gr = row0 + r;
        xsT[k * XS_STRIDE + r] = (gr < N_NODES) ? x[(size_t)gr * CH + k] : 0.f;
    }
    __syncthreads();

    int tx = tid & 31, ty = tid >> 5;
    int col0 = tx * 4, r0 = ty * 8;

    unsigned long long acc[4][4];    // [row_pair][col], f32x2 packed
#pragma unroll
    for (int p = 0; p < 4; p++)
#pragma unroll
        for (int j = 0; j < 4; j++) acc[p][j] = 0ull;  // {0.f, 0.f}

#pragma unroll 8
    for (int k = 0; k < CH; k++) {
        float4 w = *(const float4*)&Wsh[k * CH + col0];
        ulonglong2 xa = *(const ulonglong2*)&xsT[k * XS_STRIDE + r0];
        ulonglong2 xb = *(const ulonglong2*)&xsT[k * XS_STRIDE + r0 + 4];
        unsigned long long xp[4] = {xa.x, xa.y, xb.x, xb.y};
        unsigned long long wd[4];
        DUPF(wd[0], w.x); DUPF(wd[1], w.y);
        DUPF(wd[2], w.z); DUPF(wd[3], w.w);
#pragma unroll
        for (int p = 0; p < 4; p++) {
            FMA2(acc[p][0], xp[p], wd[0]);
            FMA2(acc[p][1], xp[p], wd[1]);
            FMA2(acc[p][2], xp[p], wd[2]);
            FMA2(acc[p][3], xp[p], wd[3]);
        }
    }

#pragma unroll
    for (int p = 0; p < 4; p++) {
        unsigned lo[4], hi[4];
#pragma unroll
        for (int j = 0; j < 4; j++) UNPACK2(lo[j], hi[j], acc[p][j]);
        int re = row0 + r0 + 2 * p;      // even row of the pair
        if (re < N_NODES) {
            __half2 e01 = __floats2half2_rn(__uint_as_float(lo[0]), __uint_as_float(lo[1]));
            __half2 e23 = __floats2half2_rn(__uint_as_float(lo[2]), __uint_as_float(lo[3]));
            uint2 st = make_uint2(*(unsigned*)&e01, *(unsigned*)&e23);
            *(uint2*)&g_h[(size_t)re * CH + col0] = st;
        }
        int ro = re + 1;
        if (ro < N_NODES) {
            __half2 o01 = __floats2half2_rn(__uint_as_float(hi[0]), __uint_as_float(hi[1]));
            __half2 o23 = __floats2half2_rn(__uint_as_float(hi[2]), __uint_as_float(hi[3]));
            uint2 st = make_uint2(*(unsigned*)&o01, *(unsigned*)&o23);
            *(uint2*)&g_h[(size_t)ro * CH + col0] = st;
        }
    }
}

// ---------------- aggregation + bias + relu + pooled max (fused) -----------
// Warp per dst node reading fp16 h (half the L2 traffic of fp32); block
// (16 warps) reduces pooled-max in smem before the global atomics.
__global__ void __launch_bounds__(AGG_WARPS * 32) k_aggregate(
        const float* __restrict__ b1) {
    __shared__ float sval[AGG_WARPS * CH];
    __shared__ int sgid[AGG_WARPS];
    int tid = threadIdx.x;
    int w = tid >> 5, lane = tid & 31;
    int d = blockIdx.x * AGG_WARPS + w;              // < N_NODES (50000 % 16 == 0)

    float di = g_dinv[d];
    const uint2* __restrict__ h2 = (const uint2*)g_h;  // 4 channels per uint2

    uint2 hs = h2[(size_t)d * 32 + lane];            // self loop
    float2 s01 = __half22float2(*(__half2*)&hs.x);
    float2 s23 = __half22float2(*(__half2*)&hs.y);
    float ax = s01.x * di, ay = s01.y * di, az = s23.x * di, aw = s23.y * di;

    int e0 = g_cstart[d], e1 = g_cstart[d + 1];
    int e = e0;
    for (; e + 1 < e1; e += 2) {
        int sA = g_csr_src[e], sB = g_csr_src[e + 1];
        float wA = g_dinv[sA], wB = g_dinv[sB];
        uint2 hA = h2[(size_t)sA * 32 + lane];
        uint2 hB = h2[(size_t)sB * 32 + lane];
        float2 a01 = __half22float2(*(__half2*)&hA.x);
        float2 a23 = __half22float2(*(__half2*)&hA.y);
        float2 b01 = __half22float2(*(__half2*)&hB.x);
        float2 b23 = __half22float2(*(__half2*)&hB.y);
        ax = fmaf(wA, a01.x, ax); ay = fmaf(wA, a01.y, ay);
        az = fmaf(wA, a23.x, az); aw = fmaf(wA, a23.y, aw);
        ax = fmaf(wB, b01.x, ax); ay = fmaf(wB, b01.y, ay);
        az = fmaf(wB, b23.x, az); aw = fmaf(wB, b23.y, aw);
    }
    if (e < e1) {
        int sA = g_csr_src[e];
        float wA = g_dinv[sA];
        uint2 hA = h2[(size_t)sA * 32 + lane];
        float2 a01 = __half22float2(*(__half2*)&hA.x);
        float2 a23 = __half22float2(*(__half2*)&hA.y);
        ax = fmaf(wA, a01.x, ax); ay = fmaf(wA, a01.y, ay);
        az = fmaf(wA, a23.x, az); aw = fmaf(wA, a23.y, aw);
    }

    float4 bb = *(const float4*)&b1[lane * 4];
    float4 v;
    v.x = fmaxf(fmaf(ax, di, bb.x), 0.f);
    v.y = fmaxf(fmaf(ay, di, bb.y), 0.f);
    v.z = fmaxf(fmaf(az, di, bb.z), 0.f);
    v.w = fmaxf(fmaf(aw, di, bb.w), 0.f);
    *(float4*)&sval[w * CH + lane * 4] = v;
    if (lane == 0) sgid[w] = g_batch[d];
    __syncthreads();

    if (tid < CH) {
        int c = tid;
        int curg = sgid[0];
        float m = sval[c];
        for (int ww = 1; ww < AGG_WARPS; ww++) {
            int g = sgid[ww];
            float u = sval[ww * CH + c];
            if (g == curg) {
                m = fmaxf(m, u);
            } else {
                atomicMax(&g_pooled[curg * CH + c], __float_as_uint(m));
                curg = g; m = u;
            }
        }
        atomicMax(&g_pooled[curg * CH + c], __float_as_uint(m));
    }
}

// ---------------- out = relu(pooled @ W2 + b2) -----------------------------
__global__ void k_out(const float* __restrict__ W2, const float* __restrict__ b2,
                      float* __restrict__ out) {
    __shared__ float p[CH];
    int g = blockIdx.x, c = threadIdx.x;
    p[c]      = __uint_as_float(g_pooled[g * CH + c]);
    p[c + 64] = __uint_as_float(g_pooled[g * CH + c + 64]);
    __syncthreads();
    float acc = b2[c];
#pragma unroll 8
    for (int k = 0; k < CH; k++)
        acc = fmaf(p[k], W2[k * OUTC + c], acc);
    out[g * OUTC + c] = fmaxf(acc, 0.f);
}

// ---------------- launch ---------------------------------------------------
extern "C" void kernel_launch(void* const* d_in, const int* in_sizes, int n_in,
                              void* d_out, int out_size) {
    const float *x = nullptr, *W1 = nullptr, *b1 = nullptr, *W2 = nullptr, *b2 = nullptr;
    const unsigned *ei = nullptr, *bt = nullptr;
    for (int i = 0; i < n_in; i++) {
        switch (in_sizes[i]) {
            case N_NODES * CH:    x  = (const float*)d_in[i]; break;
            case 2 * N_EDGES:     ei = (const unsigned*)d_in[i]; break;
            case N_NODES:         bt = (const unsigned*)d_in[i]; break;
            case CH * CH:         W1 = (const float*)d_in[i]; break;
            case CH:              b1 = (const float*)d_in[i]; break;
            case CH * OUTC:       W2 = (const float*)d_in[i]; break;
            case OUTC:            b2 = (const float*)d_in[i]; break;
        }
    }
    float* out = (float*)d_out;

    static cudaStream_t sB = nullptr;
    static cudaEvent_t evFork = nullptr, evJoin = nullptr;
    if (!sB) {
        cudaStreamCreateWithFlags(&sB, cudaStreamNonBlocking);
        cudaEventCreateWithFlags(&evFork, cudaEventDisableTiming);
        cudaEventCreateWithFlags(&evJoin, cudaEventDisableTiming);
        cudaFuncSetAttribute(k_gemm, cudaFuncAttributeMaxDynamicSharedMemorySize,
                             GEMM_SMEM);
    }

    // Fork: GEMM (independent of edge preprocessing) overlaps the prep chain.
    cudaEventRecord(evFork, 0);
    cudaStreamWaitEvent(sB, evFork, 0);
    k_gemm<<<(N_NODES + GEMM_ROWS - 1) / GEMM_ROWS, GEMM_THREADS, GEMM_SMEM, sB>>>(x, W1);
    cudaEventRecord(evJoin, sB);

    // Prep chain on the capture stream.
    k_init<<<SCAN_B, 256>>>(ei, bt);
    k_prep<<<(N_EDGES / 2 + 255) / 256, 256>>>(ei, bt);
    k_scan1<<<SCAN_B, 256>>>();
    k_scan2<<<1, 256>>>();
    k_scan3<<<SCAN_B, 256>>>();
    k_fill<<<(N_EDGES / 2 + 255) / 256, 256>>>();

    // Join: aggregation needs g_h from the GEMM.
    cudaStreamWaitEvent(0, evJoin, 0);
    k_aggregate<<<N_NODES / AGG_WARPS, AGG_WARPS * 32>>>(b1);
    k_out<<<NG, OUTC>>>(W2, b2, out);
}

// round 5
// speedup vs baseline: 3.8359x; 1.3662x over previous
#include <cuda_runtime.h>
#include <cuda_fp16.h>
#include <cstdint>

#define N_NODES 50000
#define N_EDGES 800000
#define CH 128
#define OUTC 64
#define NG 256
#define CAP 128                 // bucket capacity per node (P(deg>=128) ~ 1e-80)

#define AGG_WARPS 16
#define INIT_B 196              // 196*256 = 50176 >= max(N_NODES, NG*CH)

// GEMM tiling: 64 rows x 128 cols per block, 4 warps, mma.m16n8k16
#define GM 64
#define LDA 136                  // halves, 272B rows -> conflict-free ldmatrix
#define LDB 136
#define GEMM_SMEM ((GM * LDA + CH * LDB) * 2)

// ---------------- scratch (device globals; no allocation allowed) ----------
__device__ int g_is64_ei;
__device__ int g_is64_b;
__device__ int g_csr_src[N_NODES * CAP];
__device__ int g_cursor[N_NODES];
__device__ float g_dinv[N_NODES];
__device__ int g_batch[N_NODES];
__device__ __half g_h[(size_t)N_NODES * CH];
__device__ __half g_w1h[CH * CH];
__device__ unsigned g_pooled[NG * CH];

// ---------------- mma helpers ----------------------------------------------
__device__ __forceinline__ void ldsm_x4(uint32_t* r, uint32_t addr) {
    asm volatile("ldmatrix.sync.aligned.m8n8.x4.shared.b16 {%0,%1,%2,%3}, [%4];"
        : "=r"(r[0]), "=r"(r[1]), "=r"(r[2]), "=r"(r[3]) : "r"(addr));
}
__device__ __forceinline__ void ldsm_x4_t(uint32_t* r, uint32_t addr) {
    asm volatile("ldmatrix.sync.aligned.m8n8.x4.trans.shared.b16 {%0,%1,%2,%3}, [%4];"
        : "=r"(r[0]), "=r"(r[1]), "=r"(r[2]), "=r"(r[3]) : "r"(addr));
}
__device__ __forceinline__ void mma16816(float* d, const uint32_t* a, const uint32_t* b) {
    asm volatile("mma.sync.aligned.m16n8k16.row.col.f32.f16.f16.f32 "
        "{%0,%1,%2,%3}, {%4,%5,%6,%7}, {%8,%9}, {%0,%1,%2,%3};"
        : "+f"(d[0]), "+f"(d[1]), "+f"(d[2]), "+f"(d[3])
        : "r"(a[0]), "r"(a[1]), "r"(a[2]), "r"(a[3]), "r"(b[0]), "r"(b[1]));
}

// ---------------- init: sniff dtypes, init cursors + pooled ----------------
// NOTE: grid must cover max(N_NODES, NG*CH) threads (R4 bug: it covered only
// NG*CH = 32768, leaving 17232 cursors uninitialized).
__global__ void k_init(const unsigned* __restrict__ ei,
                       const unsigned* __restrict__ bt) {
    int i = blockIdx.x * blockDim.x + threadIdx.x;
    if (i < N_NODES) g_cursor[i] = i * CAP;
    if (i < NG * CH) g_pooled[i] = 0u;               // 0u == 0.0f bits
    if (blockIdx.x == 0 && threadIdx.x < 64) {
        int w = threadIdx.x >> 5, lane = threadIdx.x & 31;
        if (w == 0) {
            unsigned v = ei[2 * lane * 999 + 1];     // odd 32-bit words
            unsigned m = __ballot_sync(0xffffffffu, v == 0u);
            if (lane == 0) g_is64_ei = (m == 0xffffffffu);
        } else {
            unsigned v = bt[2001 + 2 * lane * 747];
            unsigned m = __ballot_sync(0xffffffffu, v == 0u);
            if (lane == 0) g_is64_b = (m == 0xffffffffu);
        }
    }
}

// ---------------- prep: convert + scatter edges directly into buckets ------
__global__ void k_prep(const unsigned* __restrict__ ei,
                       const unsigned* __restrict__ bt) {
    int t = blockIdx.x * blockDim.x + threadIdx.x;
    if (t < N_NODES / 2) {
        int b0, b1;
        if (g_is64_b) {
            uint4 v = ((const uint4*)bt)[t];
            b0 = (int)v.x; b1 = (int)v.z;
        } else {
            uint2 v = ((const uint2*)bt)[t];
            b0 = (int)v.x; b1 = (int)v.y;
        }
        *(int2*)&g_batch[2 * t] = make_int2(b0, b1);
    }
    if (t >= N_EDGES / 2) return;
    int s0, s1, d0, d1;
    if (g_is64_ei) {
        uint4 a = ((const uint4*)ei)[t];
        uint4 b = ((const uint4*)ei)[N_EDGES / 2 + t];
        s0 = (int)a.x; s1 = (int)a.z;
        d0 = (int)b.x; d1 = (int)b.z;
    } else {
        uint2 a = ((const uint2*)ei)[t];
        uint2 b = ((const uint2*)ei)[N_EDGES / 2 + t];
        s0 = (int)a.x; s1 = (int)a.y;
        d0 = (int)b.x; d1 = (int)b.y;
    }
    int p0 = atomicAdd(&g_cursor[d0], 1);
    g_csr_src[min(p0, d0 * CAP + CAP - 1)] = s0;     // clamp: memory safety only
    int p1 = atomicAdd(&g_cursor[d1], 1);
    g_csr_src[min(p1, d1 * CAP + CAP - 1)] = s1;
}

// ---------------- dinv = rsqrt(deg_in + 1) ---------------------------------
__global__ void k_dinv() {
    int t = blockIdx.x * blockDim.x + threadIdx.x;
    if (t >= N_NODES) return;
    int cnt = g_cursor[t] - t * CAP;
    g_dinv[t] = rsqrtf((float)(cnt + 1));
}

// ---------------- W1 -> fp16 ----------------------------------------------
__global__ void k_wconv(const float* __restrict__ W1) {
    int t = blockIdx.x * blockDim.x + threadIdx.x;   // 4096 threads, 4 elems each
    float4 v = ((const float4*)W1)[t];
    __half2 h01 = __floats2half2_rn(v.x, v.y);
    __half2 h23 = __floats2half2_rn(v.z, v.w);
    ((uint2*)g_w1h)[t] = make_uint2(*(unsigned*)&h01, *(unsigned*)&h23);
}

// ---------------- h = x @ W1 via HMMA (fp16 in, fp32 accum, fp16 out) ------
__global__ void __launch_bounds__(128) k_gemm(const float* __restrict__ x) {
    extern __shared__ __half sm[];
    __half* As = sm;                 // [GM][LDA]
    __half* Bs = sm + GM * LDA;      // [CH][LDB]
    int tid = threadIdx.x;
    int row0 = blockIdx.x * GM;

    // load x tile (fp32 -> fp16), 64x128
#pragma unroll
    for (int i = 0; i < 16; i++) {
        int idx4 = tid + i * 128;                    // float4 index in 64x32
        int r = idx4 >> 5, c4 = idx4 & 31;
        int gr = row0 + r;
        float4 v = (gr < N_NODES) ? ((const float4*)x)[(size_t)gr * 32 + c4]
                                  : make_float4(0.f, 0.f, 0.f, 0.f);
        __half2 h01 = __floats2half2_rn(v.x, v.y);
        __half2 h23 = __floats2half2_rn(v.z, v.w);
        *(uint2*)&As[r * LDA + c4 * 4] = make_uint2(*(unsigned*)&h01, *(unsigned*)&h23);
    }
    // load W1 (fp16), 128x128
#pragma unroll
    for (int i = 0; i < 16; i++) {
        int idx8 = tid + i * 128;                    // uint4 index in 128x16
        int r = idx8 >> 4, c8 = idx8 & 15;
        *(uint4*)&Bs[r * LDB + c8 * 8] = ((const uint4*)g_w1h)[(size_t)r * 16 + c8];
    }
    __syncthreads();

    int w = tid >> 5, lane = tid & 31;
    int m0 = w * 16;
    uint32_t a_base = (uint32_t)__cvta_generic_to_shared(As)
                    + ((m0 + (lane & 15)) * LDA + (lane >> 4) * 8) * 2;
    uint32_t b_base = (uint32_t)__cvta_generic_to_shared(Bs)
                    + ((lane & 15) * LDB + (lane >> 4) * 8) * 2;

    float acc[16][4];
#pragma unroll
    for (int j = 0; j < 16; j++)
#pragma unroll
        for (int q = 0; q < 4; q++) acc[j][q] = 0.f;

#pragma unroll
    for (int kk = 0; kk < 8; kk++) {
        uint32_t a[4];
        ldsm_x4(a, a_base + kk * 16 * 2);
#pragma unroll
        for (int jt = 0; jt < 8; jt++) {             // n-tile pairs (n16 each)
            uint32_t b[4];
            ldsm_x4_t(b, b_base + (kk * 16 * LDB + jt * 16) * 2);
            mma16816(acc[2 * jt], a, b);
            mma16816(acc[2 * jt + 1], a, b + 2);
        }
    }

    int r_lo = row0 + m0 + (lane >> 2);
    int r_hi = r_lo + 8;
    int cbase = (lane & 3) * 2;
#pragma unroll
    for (int j = 0; j < 16; j++) {
        int col = j * 8 + cbase;
        if (r_lo < N_NODES) {
            __half2 v = __floats2half2_rn(acc[j][0], acc[j][1]);
            *(unsigned*)&g_h[(size_t)r_lo * CH + col] = *(unsigned*)&v;
        }
        if (r_hi < N_NODES) {
            __half2 v = __floats2half2_rn(acc[j][2], acc[j][3]);
            *(unsigned*)&g_h[(size_t)r_hi * CH + col] = *(unsigned*)&v;
        }
    }
}

// ---------------- aggregation + bias + relu + pooled max (fused) -----------
__global__ void __launch_bounds__(AGG_WARPS * 32) k_aggregate(
        const float* __restrict__ b1) {
    __shared__ float sval[AGG_WARPS * CH];
    __shared__ int sgid[AGG_WARPS];
    int tid = threadIdx.x;
    int w = tid >> 5, lane = tid & 31;
    int d = blockIdx.x * AGG_WARPS + w;              // < N_NODES (50000 % 16 == 0)

    float di = g_dinv[d];
    const uint2* __restrict__ h2 = (const uint2*)g_h;

    uint2 hs = h2[(size_t)d * 32 + lane];            // self loop
    float2 s01 = __half22float2(*(__half2*)&hs.x);
    float2 s23 = __half22float2(*(__half2*)&hs.y);
    float ax = s01.x * di, ay = s01.y * di, az = s23.x * di, aw = s23.y * di;

    int e0 = d * CAP, e1 = g_cursor[d];
    int e = e0;
    for (; e + 1 < e1; e += 2) {
        int sA = g_csr_src[e], sB = g_csr_src[e + 1];
        float wA = g_dinv[sA], wB = g_dinv[sB];
        uint2 hA = h2[(size_t)sA * 32 + lane];
        uint2 hB = h2[(size_t)sB * 32 + lane];
        float2 a01 = __half22float2(*(__half2*)&hA.x);
        float2 a23 = __half22float2(*(__half2*)&hA.y);
        float2 b01 = __half22float2(*(__half2*)&hB.x);
        float2 b23 = __half22float2(*(__half2*)&hB.y);
        ax = fmaf(wA, a01.x, ax); ay = fmaf(wA, a01.y, ay);
        az = fmaf(wA, a23.x, az); aw = fmaf(wA, a23.y, aw);
        ax = fmaf(wB, b01.x, ax); ay = fmaf(wB, b01.y, ay);
        az = fmaf(wB, b23.x, az); aw = fmaf(wB, b23.y, aw);
    }
    if (e < e1) {
        int sA = g_csr_src[e];
        float wA = g_dinv[sA];
        uint2 hA = h2[(size_t)sA * 32 + lane];
        float2 a01 = __half22float2(*(__half2*)&hA.x);
        float2 a23 = __half22float2(*(__half2*)&hA.y);
        ax = fmaf(wA, a01.x, ax); ay = fmaf(wA, a01.y, ay);
        az = fmaf(wA, a23.x, az); aw = fmaf(wA, a23.y, aw);
    }

    float4 bb = *(const float4*)&b1[lane * 4];
    float4 v;
    v.x = fmaxf(fmaf(ax, di, bb.x), 0.f);
    v.y = fmaxf(fmaf(ay, di, bb.y), 0.f);
    v.z = fmaxf(fmaf(az, di, bb.z), 0.f);
    v.w = fmaxf(fmaf(aw, di, bb.w), 0.f);
    *(float4*)&sval[w * CH + lane * 4] = v;
    if (lane == 0) sgid[w] = g_batch[d];
    __syncthreads();

    if (tid < CH) {
        int c = tid;
        int curg = sgid[0];
        float m = sval[c];
        for (int ww = 1; ww < AGG_WARPS; ww++) {
            int g = sgid[ww];
            float u = sval[ww * CH + c];
            if (g == curg) {
                m = fmaxf(m, u);
            } else {
                atomicMax(&g_pooled[curg * CH + c], __float_as_uint(m));
                curg = g; m = u;
            }
        }
        atomicMax(&g_pooled[curg * CH + c], __float_as_uint(m));
    }
}

// ---------------- out = relu(pooled @ W2 + b2) -----------------------------
__global__ void k_out(const float* __restrict__ W2, const float* __restrict__ b2,
                      float* __restrict__ out) {
    __shared__ float p[CH];
    int g = blockIdx.x, c = threadIdx.x;
    p[c]      = __uint_as_float(g_pooled[g * CH + c]);
    p[c + 64] = __uint_as_float(g_pooled[g * CH + c + 64]);
    __syncthreads();
    float acc = b2[c];
#pragma unroll 8
    for (int k = 0; k < CH; k++)
        acc = fmaf(p[k], W2[k * OUTC + c], acc);
    out[g * OUTC + c] = fmaxf(acc, 0.f);
}

// ---------------- launch ---------------------------------------------------
extern "C" void kernel_launch(void* const* d_in, const int* in_sizes, int n_in,
                              void* d_out, int out_size) {
    const float *x = nullptr, *W1 = nullptr, *b1 = nullptr, *W2 = nullptr, *b2 = nullptr;
    const unsigned *ei = nullptr, *bt = nullptr;
    for (int i = 0; i < n_in; i++) {
        switch (in_sizes[i]) {
            case N_NODES * CH:    x  = (const float*)d_in[i]; break;
            case 2 * N_EDGES:     ei = (const unsigned*)d_in[i]; break;
            case N_NODES:         bt = (const unsigned*)d_in[i]; break;
            case CH * CH:         W1 = (const float*)d_in[i]; break;
            case CH:              b1 = (const float*)d_in[i]; break;
            case CH * OUTC:       W2 = (const float*)d_in[i]; break;
            case OUTC:            b2 = (const float*)d_in[i]; break;
        }
    }
    float* out = (float*)d_out;

    static cudaStream_t sB = nullptr;
    static cudaEvent_t evFork = nullptr, evJoin = nullptr;
    if (!sB) {
        cudaStreamCreateWithFlags(&sB, cudaStreamNonBlocking);
        cudaEventCreateWithFlags(&evFork, cudaEventDisableTiming);
        cudaEventCreateWithFlags(&evJoin, cudaEventDisableTiming);
        cudaFuncSetAttribute(k_gemm, cudaFuncAttributeMaxDynamicSharedMemorySize,
                             GEMM_SMEM);
    }

    // Fork: W-convert + tensor-core GEMM overlap the edge preprocessing.
    cudaEventRecord(evFork, 0);
    cudaStreamWaitEvent(sB, evFork, 0);
    k_wconv<<<16, 256, 0, sB>>>(W1);
    k_gemm<<<(N_NODES + GM - 1) / GM, 128, GEMM_SMEM, sB>>>(x);
    cudaEventRecord(evJoin, sB);

    // Prep chain on the capture stream (bucket CSR: no prefix scan).
    k_init<<<INIT_B, 256>>>(ei, bt);
    k_prep<<<(N_EDGES / 2 + 255) / 256, 256>>>(ei, bt);
    k_dinv<<<(N_NODES + 255) / 256, 256>>>();

    // Join: aggregation needs g_h from the GEMM.
    cudaStreamWaitEvent(0, evJoin, 0);
    k_aggregate<<<N_NODES / AGG_WARPS, AGG_WARPS * 32>>>(b1);
    k_out<<<NG, OUTC>>>(W2, b2, out);
}